// round 15
// baseline (speedup 1.0000x reference)
#include <cuda_runtime.h>
#include <cstdint>

#define DEV_INLINE __device__ __forceinline__

constexpr int N  = 256;
constexpr int T  = 1024;
constexpr int P  = 4;
constexpr int AS = T + P;        // alpha row stride = 1028 floats
constexpr int Tp = T - P;        // 1020

// ---- btl: linear-sweep blocks, block = (i, 8-j-group) x full t ----
constexpr int BTL_BLOCKS = 4192;
constexpr int K1_BTL = 2048;                     // covered by 1-in-3 region
constexpr int K2_BTL = BTL_BLOCKS - K1_BTL;      // 2144

// ---- AR partial tiling: (t-group x n-chunk), full m per block ----
constexpr int SP_TT   = 16;                      // t per group
constexpr int SP_TG   = 64;                      // 64*16 = 1024 >= 1020
constexpr int SP_NC   = 16;                      // n chunks of 16
constexpr int ARP_BLOCKS = SP_TG * SP_NC;        // 1024 (same as R13)
constexpr int CMB_BLOCKS = SP_TG;                // 64

constexpr int K1_GRID = 3072;                    // 2048 btl + 1024 arp, 1-in-3
constexpr int K2_GRID = K2_BTL + CMB_BLOCKS;     // 2208

constexpr int SAT_W = 260;                       // padded row (bank-shift, 16B mult)

__device__ float  g_btl_partial[BTL_BLOCKS];
__device__ double g_ar_partial[CMB_BLOCKS];
__device__ float4 g_phiT4[N * N];                // phiT4[m][n] = {Phi[k][n][m]}
__device__ float  g_s12[SP_TG * SP_NC * SP_TT * 2];  // 128 KB: (s1, s2) per (tg,nc,tt)

struct SmemBTL {
    float red[8];
    float s1s[SP_TT];
    float s2s[SP_TT];
};
struct __align__(16) SmemARP {
    float sat[20][SAT_W];   // sat[c][m] = alpha[m][t0+c], ~20.8 KB
};
union SmemU { SmemBTL b; SmemARP p; };

DEV_INLINE float warpReduce(float v) {
    #pragma unroll
    for (int o = 16; o > 0; o >>= 1)
        v += __shfl_xor_sync(0xffffffffu, v, o);
    return v;
}

DEV_INLINE float blockReduce(float v, float* red) {
    v = warpReduce(v);
    if ((threadIdx.x & 31) == 0) red[threadIdx.x >> 5] = v;
    __syncthreads();
    float r = 0.f;
    if (threadIdx.x < 32) {
        r = (threadIdx.x < 8) ? red[threadIdx.x] : 0.f;
        #pragma unroll
        for (int o = 4; o > 0; o >>= 1)
            r += __shfl_xor_sync(0xffffffffu, r, o);
    }
    __syncthreads();
    return r;
}

// prefix count of btl blocks before row i (analytic)
DEV_INLINE int btl_cum(int i) {
    int m = i >> 3;
    return 32 * i - (4 * m * (m - 1) + (i - 8 * m + 1) * m);
}

DEV_INLINE float4 exp4(float4 v) {
    return make_float4(__expf(v.x), __expf(v.y), __expf(v.z), __expf(v.w));
}

// ---------------- BTL (proven: 67% DRAM, 5.3 TB/s) ----------------
DEV_INLINE void btl_block(const float* __restrict__ Z,
                          const float* __restrict__ W,
                          const float* __restrict__ alpha,
                          SmemBTL& s, int bid) {
    int i = 0;
    #pragma unroll
    for (int step = 128; step > 0; step >>= 1) {
        int cand = i + step;
        if (cand <= 255 && btl_cum(cand) <= bid) i = cand;
    }
    const int jg = ((i + 1) >> 3) + (bid - btl_cum(i));
    const int j0 = jg * 8;
    const bool partial = (j0 <= i);

    const int tid = threadIdx.x;

    const float4* a4 = (const float4*)(alpha);
    const float4 si4 = a4[(i * AS + P) / 4 + tid];
    const float4 ei4 = exp4(si4);

    const float4* Z4 = (const float4*)Z;
    const float4* W4 = (const float4*)W;
    const size_t rowbase = (size_t)(i * N + j0) * (T / 4) + tid;

    float acc0 = 0.f, acc1 = 0.f;

    #pragma unroll
    for (int jb = 0; jb < 8; jb += 2) {
        float4 sjA = a4[((j0 + jb)     * AS + P) / 4 + tid];
        float4 sjB = a4[((j0 + jb + 1) * AS + P) / 4 + tid];

        float4 zA = __ldcs(Z4 + rowbase + (size_t)(jb)     * (T / 4));
        float4 zB = __ldcs(Z4 + rowbase + (size_t)(jb + 1) * (T / 4));
        float4 wA = __ldcs(W4 + rowbase + (size_t)(jb)     * (T / 4));
        float4 wB = __ldcs(W4 + rowbase + (size_t)(jb + 1) * (T / 4));

        float4 lA, lB;
        lA.x = __logf(ei4.x + __expf(sjA.x));
        lA.y = __logf(ei4.y + __expf(sjA.y));
        lA.z = __logf(ei4.z + __expf(sjA.z));
        lA.w = __logf(ei4.w + __expf(sjA.w));
        lB.x = __logf(ei4.x + __expf(sjB.x));
        lB.y = __logf(ei4.y + __expf(sjB.y));
        lB.z = __logf(ei4.z + __expf(sjB.z));
        lB.w = __logf(ei4.w + __expf(sjB.w));

        if (partial) {
            float mA = (j0 + jb     > i) ? 1.f : 0.f;
            float mB = (j0 + jb + 1 > i) ? 1.f : 0.f;
            zA.x *= mA; zA.y *= mA; zA.z *= mA; zA.w *= mA;
            wA.x *= mA; wA.y *= mA; wA.z *= mA; wA.w *= mA;
            zB.x *= mB; zB.y *= mB; zB.z *= mB; zB.w *= mB;
            wB.x *= mB; wB.y *= mB; wB.z *= mB; wB.w *= mB;
        }

        acc0 = fmaf(zA.x, si4.x - lA.x, acc0);
        acc0 = fmaf(zA.y, si4.y - lA.y, acc0);
        acc0 = fmaf(zA.z, si4.z - lA.z, acc0);
        acc0 = fmaf(zA.w, si4.w - lA.w, acc0);
        acc1 = fmaf(wA.x, sjA.x - lA.x, acc1);
        acc1 = fmaf(wA.y, sjA.y - lA.y, acc1);
        acc1 = fmaf(wA.z, sjA.z - lA.z, acc1);
        acc1 = fmaf(wA.w, sjA.w - lA.w, acc1);
        acc0 = fmaf(zB.x, si4.x - lB.x, acc0);
        acc0 = fmaf(zB.y, si4.y - lB.y, acc0);
        acc0 = fmaf(zB.z, si4.z - lB.z, acc0);
        acc0 = fmaf(zB.w, si4.w - lB.w, acc0);
        acc1 = fmaf(wB.x, sjB.x - lB.x, acc1);
        acc1 = fmaf(wB.y, sjB.y - lB.y, acc1);
        acc1 = fmaf(wB.z, sjB.z - lB.z, acc1);
        acc1 = fmaf(wB.w, sjB.w - lB.w, acc1);
    }

    float tot = blockReduce(acc0 + acc1, s.red);
    if (tid == 0) g_btl_partial[bid] = tot;
}

// ---------------- AR partial: (tg, nc) -> complete S + quadratic stats ---------
// Each block: 16 n x 16 t tile of S, full m = 0..255. 1024 FMA/thread.
DEV_INLINE void arp_block(const float* __restrict__ alpha,
                          SmemARP& s, int pbid) {
    const int tg = pbid >> 4;          // 0..63
    const int nc = pbid & 15;          // 0..15
    const int t0 = tg * SP_TT;
    const int n0 = nc * 16;
    const int tid = threadIdx.x;

    // stage alpha transposed: sat[c][m] = alpha[m][t0+c], c in [0,20)
    {
        const float4* asrc = (const float4*)(alpha + tid * AS + t0); // 16B aligned
        #pragma unroll
        for (int c4 = 0; c4 < 5; ++c4) {
            float4 v = asrc[c4];
            s.sat[c4 * 4 + 0][tid] = v.x;
            s.sat[c4 * 4 + 1][tid] = v.y;
            s.sat[c4 * 4 + 2][tid] = v.z;
            s.sat[c4 * 4 + 3][tid] = v.w;
        }
    }
    __syncthreads();

    const int nl = tid & 15;           // n within chunk
    const int tt = tid >> 4;           // t within group
    const int n  = n0 + nl;

    float acc = 0.f;
    #pragma unroll 4
    for (int m = 0; m < N; m += 4) {
        float4 p0 = g_phiT4[(m + 0) * N + n];
        float4 p1 = g_phiT4[(m + 1) * N + n];
        float4 p2 = g_phiT4[(m + 2) * N + n];
        float4 p3 = g_phiT4[(m + 3) * N + n];
        float4 a0 = *(const float4*)&s.sat[tt + 0][m];   // alpha[m..m+3][t0+tt+0]
        float4 a1 = *(const float4*)&s.sat[tt + 1][m];
        float4 a2 = *(const float4*)&s.sat[tt + 2][m];
        float4 a3 = *(const float4*)&s.sat[tt + 3][m];
        acc = fmaf(p0.x, a0.x, acc); acc = fmaf(p0.y, a1.x, acc);
        acc = fmaf(p0.z, a2.x, acc); acc = fmaf(p0.w, a3.x, acc);
        acc = fmaf(p1.x, a0.y, acc); acc = fmaf(p1.y, a1.y, acc);
        acc = fmaf(p1.z, a2.y, acc); acc = fmaf(p1.w, a3.y, acc);
        acc = fmaf(p2.x, a0.z, acc); acc = fmaf(p2.y, a1.z, acc);
        acc = fmaf(p2.z, a2.z, acc); acc = fmaf(p2.w, a3.z, acc);
        acc = fmaf(p3.x, a0.w, acc); acc = fmaf(p3.y, a1.w, acc);
        acc = fmaf(p3.z, a2.w, acc); acc = fmaf(p3.w, a3.w, acc);
    }

    // S complete for (n, t0+tt). Reduce (S, S^2) over the 16-lane n-group.
    float s1 = acc, s2 = acc * acc;
    #pragma unroll
    for (int o = 8; o > 0; o >>= 1) {
        s1 += __shfl_xor_sync(0xffffffffu, s1, o);
        s2 += __shfl_xor_sync(0xffffffffu, s2, o);
    }
    if (nl == 0) {
        int base = ((tg * SP_NC + nc) * SP_TT + tt) * 2;
        g_s12[base + 0] = s1;
        g_s12[base + 1] = s2;
    }
}

// ---------------- Combine: sum 16 n-chunks, quadratic formula ----------------
DEV_INLINE void combine_block(const float* __restrict__ alpha,
                              SmemBTL& s, int tg) {
    const int t0  = tg * SP_TT;
    const int tid = threadIdx.x;        // = n for alpha moments

    // gather S-stats: thread (tt = tid>>4, nc = tid&15)
    {
        const int tt = tid >> 4;
        const int nc = tid & 15;
        int base = ((tg * SP_NC + nc) * SP_TT + tt) * 2;
        float s1v = g_s12[base + 0];
        float s2v = g_s12[base + 1];
        #pragma unroll
        for (int o = 8; o > 0; o >>= 1) {
            s1v += __shfl_xor_sync(0xffffffffu, s1v, o);
            s2v += __shfl_xor_sync(0xffffffffu, s2v, o);
        }
        if (nc == 0) { s.s1s[tt] = s1v; s.s2s[tt] = s2v; }
    }
    __syncthreads();

    double part = 0.0;
    #pragma unroll 1
    for (int tt = 0; tt < SP_TT; ++tt) {
        float A = alpha[tid * AS + P + t0 + tt];
        float a1 = blockReduce(A, s.red);
        float a2 = blockReduce(A * A, s.red);
        if (tid == 0 && (t0 + tt) < Tp) {
            part += (double)N * (double)s.s2s[tt]
                  - 2.0 * (double)s.s1s[tt] * (double)a1
                  + (double)N * (double)a2;
        }
    }
    if (tid == 0) g_ar_partial[tg] = part;
}

// ---------------- K0: pack Phi -> phiT4[m][n] = {Phi[k][n][m]} ----------------
__global__ __launch_bounds__(256) void pack_kernel(const float* __restrict__ Phi) {
    __shared__ float tile[4][32][33];
    const int mb = blockIdx.x * 32;
    const int nb = blockIdx.y * 32;
    const int tx = threadIdx.x & 31;
    const int ty = threadIdx.x >> 5;   // 0..7

    #pragma unroll
    for (int k = 0; k < 4; ++k)
        #pragma unroll
        for (int r = 0; r < 4; ++r)
            tile[k][ty + r * 8][tx] = Phi[(k << 16) + (nb + ty + r * 8) * N + (mb + tx)];
    __syncthreads();

    #pragma unroll
    for (int r = 0; r < 4; ++r) {
        const int ml = ty + r * 8;
        const int nl = tx;
        float4 v = make_float4(tile[0][nl][ml], tile[1][nl][ml],
                               tile[2][nl][ml], tile[3][nl][ml]);
        g_phiT4[(mb + ml) * N + (nb + nl)] = v;
    }
}

// ---------------- K1: 2048 btl + 1024 arp, exact 1-in-3 interleave (R13) -------
__global__ __launch_bounds__(256, 4) void mega_kernel_a(const float* __restrict__ Z,
                                                        const float* __restrict__ W,
                                                        const float* __restrict__ alpha) {
    __shared__ SmemU sm;
    const int bid = blockIdx.x;        // grid = 3072
    const int q = bid / 3, r = bid - q * 3;
    if (r == 2) arp_block(alpha, sm.p, q);
    else        btl_block(Z, W, alpha, sm.b, q * 2 + r);
}

// ---------------- K2: 2144 btl + 64 combine (bid % 32 == 31 in first 2048) -----
__global__ __launch_bounds__(256, 4) void mega_kernel_b(const float* __restrict__ Z,
                                                        const float* __restrict__ W,
                                                        const float* __restrict__ alpha) {
    __shared__ SmemU sm;
    const int bid = blockIdx.x;        // grid = 2208 = 2144 btl + 64 combine
    if (bid < 2048 && (bid & 31) == 31) {
        combine_block(alpha, sm.b, bid >> 5);
    } else {
        int btl_idx = (bid < 2048) ? (bid - (bid >> 5)) : (bid - 64);
        btl_block(Z, W, alpha, sm.b, K1_BTL + btl_idx);   // [2048, 4192)
    }
}

__global__ __launch_bounds__(256) void finalize_kernel(float* __restrict__ out) {
    __shared__ double sred[8];
    __shared__ double sred2[8];
    const int tid  = threadIdx.x;
    const int lane = tid & 31;
    const int wid  = tid >> 5;

    const float4* p4 = (const float4*)g_btl_partial;
    double s = 0.0;
    #pragma unroll 1
    for (int i = tid; i < BTL_BLOCKS / 4; i += 256) {
        float4 v = p4[i];
        s += (double)((v.x + v.y) + (v.z + v.w));
    }
    double s2 = (tid < CMB_BLOCKS) ? g_ar_partial[tid] : 0.0;

    #pragma unroll
    for (int o = 16; o > 0; o >>= 1) {
        s  += __shfl_xor_sync(0xffffffffu, s,  o);
        s2 += __shfl_xor_sync(0xffffffffu, s2, o);
    }
    if (lane == 0) { sred[wid] = s; sred2[wid] = s2; }
    __syncthreads();
    if (tid == 0) {
        double a = 0.0, b = 0.0;
        #pragma unroll
        for (int wq = 0; wq < 8; ++wq) { a += sred[wq]; b += sred2[wq]; }
        out[0] = (float)a;
        out[1] = (float)b;
    }
}

extern "C" void kernel_launch(void* const* d_in, const int* in_sizes, int n_in,
                              void* d_out, int out_size) {
    const float* Z     = (const float*)d_in[0];
    const float* W     = (const float*)d_in[1];
    const float* Phi   = (const float*)d_in[2];
    const float* alpha = (const float*)d_in[3];
    float* out = (float*)d_out;

    pack_kernel<<<dim3(8, 8), 256>>>(Phi);
    mega_kernel_a<<<K1_GRID, 256>>>(Z, W, alpha);
    mega_kernel_b<<<K2_GRID, 256>>>(Z, W, alpha);
    finalize_kernel<<<1, 256>>>(out);
}

// round 16
// speedup vs baseline: 1.7896x; 1.7896x over previous
#include <cuda_runtime.h>
#include <cstdint>

#define DEV_INLINE __device__ __forceinline__

constexpr int N  = 256;
constexpr int T  = 1024;
constexpr int P  = 4;
constexpr int AS = T + P;        // alpha row stride = 1028 floats
constexpr int Tp = T - P;        // 1020

// ---- btl: linear-sweep blocks, block = (i, 8-j-group) x full t ----
constexpr int BTL_BLOCKS = 4192;

// ---- AR partial tiling: (t-group x m-chunk of 16) — R13-proven ----
constexpr int SP_TT   = 16;                      // t per group
constexpr int SP_TG   = 64;                      // 64*16 = 1024 >= 1020
constexpr int SP_MC   = 16;                      // m chunks of 16
constexpr int ARP_BLOCKS = SP_TG * SP_MC;        // 1024
constexpr int CMB_BLOCKS = SP_TG * SP_TT;        // 1024 (one per (tg,tt))

// MEGA: 4192 btl + 1024 arp, 1-in-5 confined interleave + pure-btl tail
constexpr int MEGA_GRID = BTL_BLOCKS + ARP_BLOCKS;   // 5216

__device__ float  g_btl_partial[BTL_BLOCKS];
__device__ double g_ar_partial[CMB_BLOCKS];
__device__ float4 g_phiT4[N * N];                    // phiT4[m][n] = {Phi[k][n][m]}
__device__ float  g_Spart[ARP_BLOCKS * SP_TT * N];   // 16 MB scratch

struct SmemBTL {
    float red[8];
};
struct SmemARP {
    float sa[16][20];   // alpha[m0+r][t0+c]
};
union SmemU { SmemBTL b; SmemARP p; };

DEV_INLINE float warpReduce(float v) {
    #pragma unroll
    for (int o = 16; o > 0; o >>= 1)
        v += __shfl_xor_sync(0xffffffffu, v, o);
    return v;
}

DEV_INLINE float blockReduce(float v, float* red) {
    v = warpReduce(v);
    if ((threadIdx.x & 31) == 0) red[threadIdx.x >> 5] = v;
    __syncthreads();
    float r = 0.f;
    if (threadIdx.x < 32) {
        r = (threadIdx.x < 8) ? red[threadIdx.x] : 0.f;
        #pragma unroll
        for (int o = 4; o > 0; o >>= 1)
            r += __shfl_xor_sync(0xffffffffu, r, o);
    }
    __syncthreads();
    return r;
}

// prefix count of btl blocks before row i (analytic)
DEV_INLINE int btl_cum(int i) {
    int m = i >> 3;
    return 32 * i - (4 * m * (m - 1) + (i - 8 * m + 1) * m);
}

DEV_INLINE float4 exp4(float4 v) {
    return make_float4(__expf(v.x), __expf(v.y), __expf(v.z), __expf(v.w));
}

// ---------------- BTL (proven: 67% DRAM, 5.3 TB/s) ----------------
DEV_INLINE void btl_block(const float* __restrict__ Z,
                          const float* __restrict__ W,
                          const float* __restrict__ alpha,
                          SmemBTL& s, int bid) {
    int i = 0;
    #pragma unroll
    for (int step = 128; step > 0; step >>= 1) {
        int cand = i + step;
        if (cand <= 255 && btl_cum(cand) <= bid) i = cand;
    }
    const int jg = ((i + 1) >> 3) + (bid - btl_cum(i));
    const int j0 = jg * 8;
    const bool partial = (j0 <= i);

    const int tid = threadIdx.x;

    const float4* a4 = (const float4*)(alpha);
    const float4 si4 = a4[(i * AS + P) / 4 + tid];
    const float4 ei4 = exp4(si4);

    const float4* Z4 = (const float4*)Z;
    const float4* W4 = (const float4*)W;
    const size_t rowbase = (size_t)(i * N + j0) * (T / 4) + tid;

    float acc0 = 0.f, acc1 = 0.f;

    #pragma unroll
    for (int jb = 0; jb < 8; jb += 2) {
        float4 sjA = a4[((j0 + jb)     * AS + P) / 4 + tid];
        float4 sjB = a4[((j0 + jb + 1) * AS + P) / 4 + tid];

        float4 zA = __ldcs(Z4 + rowbase + (size_t)(jb)     * (T / 4));
        float4 zB = __ldcs(Z4 + rowbase + (size_t)(jb + 1) * (T / 4));
        float4 wA = __ldcs(W4 + rowbase + (size_t)(jb)     * (T / 4));
        float4 wB = __ldcs(W4 + rowbase + (size_t)(jb + 1) * (T / 4));

        float4 lA, lB;
        lA.x = __logf(ei4.x + __expf(sjA.x));
        lA.y = __logf(ei4.y + __expf(sjA.y));
        lA.z = __logf(ei4.z + __expf(sjA.z));
        lA.w = __logf(ei4.w + __expf(sjA.w));
        lB.x = __logf(ei4.x + __expf(sjB.x));
        lB.y = __logf(ei4.y + __expf(sjB.y));
        lB.z = __logf(ei4.z + __expf(sjB.z));
        lB.w = __logf(ei4.w + __expf(sjB.w));

        if (partial) {
            float mA = (j0 + jb     > i) ? 1.f : 0.f;
            float mB = (j0 + jb + 1 > i) ? 1.f : 0.f;
            zA.x *= mA; zA.y *= mA; zA.z *= mA; zA.w *= mA;
            wA.x *= mA; wA.y *= mA; wA.z *= mA; wA.w *= mA;
            zB.x *= mB; zB.y *= mB; zB.z *= mB; zB.w *= mB;
            wB.x *= mB; wB.y *= mB; wB.z *= mB; wB.w *= mB;
        }

        acc0 = fmaf(zA.x, si4.x - lA.x, acc0);
        acc0 = fmaf(zA.y, si4.y - lA.y, acc0);
        acc0 = fmaf(zA.z, si4.z - lA.z, acc0);
        acc0 = fmaf(zA.w, si4.w - lA.w, acc0);
        acc1 = fmaf(wA.x, sjA.x - lA.x, acc1);
        acc1 = fmaf(wA.y, sjA.y - lA.y, acc1);
        acc1 = fmaf(wA.z, sjA.z - lA.z, acc1);
        acc1 = fmaf(wA.w, sjA.w - lA.w, acc1);
        acc0 = fmaf(zB.x, si4.x - lB.x, acc0);
        acc0 = fmaf(zB.y, si4.y - lB.y, acc0);
        acc0 = fmaf(zB.z, si4.z - lB.z, acc0);
        acc0 = fmaf(zB.w, si4.w - lB.w, acc0);
        acc1 = fmaf(wB.x, sjB.x - lB.x, acc1);
        acc1 = fmaf(wB.y, sjB.y - lB.y, acc1);
        acc1 = fmaf(wB.z, sjB.z - lB.z, acc1);
        acc1 = fmaf(wB.w, sjB.w - lB.w, acc1);
    }

    float tot = blockReduce(acc0 + acc1, s.red);
    if (tid == 0) g_btl_partial[bid] = tot;
}

// ---------------- AR partial: (tg, mc of 16 m) -> Spart (R13-proven) ------------
DEV_INLINE void arp_block(const float* __restrict__ alpha,
                          SmemARP& s, int pbid) {
    const int tg = pbid >> 4;          // 0..63
    const int mc = pbid & 15;          // 0..15
    const int t0 = tg * SP_TT;
    const int m0 = mc * 16;
    const int tid = threadIdx.x;       // = n

    // stage alpha[m0+r][t0+c], 320 cells, grid-stride
    #pragma unroll
    for (int idx = tid; idx < 16 * 20; idx += 256) {
        int r = idx / 20, c = idx - r * 20;
        s.sa[r][c] = alpha[(m0 + r) * AS + t0 + c];   // max col 1027 < 1028
    }
    __syncthreads();

    float acc[SP_TT];
    #pragma unroll
    for (int tt = 0; tt < SP_TT; ++tt) acc[tt] = 0.f;

    #pragma unroll 2
    for (int m = 0; m < 16; ++m) {
        float4 p = g_phiT4[(m0 + m) * N + tid];     // coalesced LDG.128, 64 KB/block
        float av[SP_TT + 3];
        #pragma unroll
        for (int c = 0; c < SP_TT + 3; ++c) av[c] = s.sa[m][c];
        #pragma unroll
        for (int tt = 0; tt < SP_TT; ++tt) {
            acc[tt] = fmaf(p.x, av[tt],     acc[tt]);
            acc[tt] = fmaf(p.y, av[tt + 1], acc[tt]);
            acc[tt] = fmaf(p.z, av[tt + 2], acc[tt]);
            acc[tt] = fmaf(p.w, av[tt + 3], acc[tt]);
        }
    }

    float* dst = g_Spart + (size_t)pbid * SP_TT * N + tid;
    #pragma unroll
    for (int tt = 0; tt < SP_TT; ++tt)
        dst[tt * N] = acc[tt];          // coalesced STG.32
}

// ---------------- K0: pack Phi -> phiT4[m][n] = {Phi[k][n][m]} ----------------
__global__ __launch_bounds__(256) void pack_kernel(const float* __restrict__ Phi) {
    __shared__ float tile[4][32][33];
    const int mb = blockIdx.x * 32;
    const int nb = blockIdx.y * 32;
    const int tx = threadIdx.x & 31;
    const int ty = threadIdx.x >> 5;   // 0..7

    #pragma unroll
    for (int k = 0; k < 4; ++k)
        #pragma unroll
        for (int r = 0; r < 4; ++r)
            tile[k][ty + r * 8][tx] = Phi[(k << 16) + (nb + ty + r * 8) * N + (mb + tx)];
    __syncthreads();

    #pragma unroll
    for (int r = 0; r < 4; ++r) {
        const int ml = ty + r * 8;
        const int nl = tx;
        float4 v = make_float4(tile[0][nl][ml], tile[1][nl][ml],
                               tile[2][nl][ml], tile[3][nl][ml]);
        g_phiT4[(mb + ml) * N + (nb + nl)] = v;
    }
}

// ---------------- MEGA: 4192 btl + 1024 arp, 1-in-5 confined interleave --------
// bid < 5120: r = bid%5; r==4 -> arp(bid/5) [exactly 1024]; else btl((bid/5)*4+r)
//             [bijective onto 0..4095]
// bid >= 5120: btl(4096 + bid - 5120)  [4096..4191] -> pure-btl tail
__global__ __launch_bounds__(256, 4) void mega_kernel(const float* __restrict__ Z,
                                                      const float* __restrict__ W,
                                                      const float* __restrict__ alpha) {
    __shared__ SmemU sm;
    const int bid = blockIdx.x;        // grid = 5216
    if (bid < 5120) {
        const int q = bid / 5, r = bid - q * 5;
        if (r == 4) arp_block(alpha, sm.p, q);
        else        btl_block(Z, W, alpha, sm.b, q * 4 + r);
    } else {
        btl_block(Z, W, alpha, sm.b, 4096 + (bid - 5120));
    }
}

// ---------------- Combine: 1024 blocks, one (tg,tt) each -----------------------
__global__ __launch_bounds__(256) void combine_kernel(const float* __restrict__ alpha) {
    __shared__ float red[8];
    const int cb  = blockIdx.x;        // = tg*16 + tt
    const int tg  = cb >> 4;
    const int tt  = cb & 15;
    const int t0  = tg * SP_TT;
    const int tid = threadIdx.x;       // = n

    float S = 0.f;
    const float* sp = g_Spart + ((size_t)(tg * SP_MC) * SP_TT + tt) * N + tid;
    #pragma unroll
    for (int mc = 0; mc < SP_MC; ++mc)
        S += sp[(size_t)mc * SP_TT * N];
    float A = alpha[tid * AS + P + t0 + tt];

    float s1 = blockReduce(S, red);
    float s2 = blockReduce(S * S, red);
    float a1 = blockReduce(A, red);
    float a2 = blockReduce(A * A, red);
    if (tid == 0) {
        double part = 0.0;
        if ((t0 + tt) < Tp) {
            part = (double)N * (double)s2
                 - 2.0 * (double)s1 * (double)a1
                 + (double)N * (double)a2;
        }
        g_ar_partial[cb] = part;
    }
}

__global__ __launch_bounds__(256) void finalize_kernel(float* __restrict__ out) {
    __shared__ double sred[8];
    __shared__ double sred2[8];
    const int tid  = threadIdx.x;
    const int lane = tid & 31;
    const int wid  = tid >> 5;

    const float4* p4 = (const float4*)g_btl_partial;
    double s = 0.0;
    #pragma unroll 1
    for (int i = tid; i < BTL_BLOCKS / 4; i += 256) {
        float4 v = p4[i];
        s += (double)((v.x + v.y) + (v.z + v.w));
    }
    double s2 = 0.0;
    #pragma unroll
    for (int i = tid; i < CMB_BLOCKS; i += 256)
        s2 += g_ar_partial[i];

    #pragma unroll
    for (int o = 16; o > 0; o >>= 1) {
        s  += __shfl_xor_sync(0xffffffffu, s,  o);
        s2 += __shfl_xor_sync(0xffffffffu, s2, o);
    }
    if (lane == 0) { sred[wid] = s; sred2[wid] = s2; }
    __syncthreads();
    if (tid == 0) {
        double a = 0.0, b = 0.0;
        #pragma unroll
        for (int wq = 0; wq < 8; ++wq) { a += sred[wq]; b += sred2[wq]; }
        out[0] = (float)a;
        out[1] = (float)b;
    }
}

extern "C" void kernel_launch(void* const* d_in, const int* in_sizes, int n_in,
                              void* d_out, int out_size) {
    const float* Z     = (const float*)d_in[0];
    const float* W     = (const float*)d_in[1];
    const float* Phi   = (const float*)d_in[2];
    const float* alpha = (const float*)d_in[3];
    float* out = (float*)d_out;

    pack_kernel<<<dim3(8, 8), 256>>>(Phi);
    mega_kernel<<<MEGA_GRID, 256>>>(Z, W, alpha);
    combine_kernel<<<CMB_BLOCKS, 256>>>(alpha);
    finalize_kernel<<<1, 256>>>(out);
}